// round 9
// baseline (speedup 1.0000x reference)
#include <cuda_runtime.h>
#include <cuda_bf16.h>
#include <cstdint>

// ---------------------------------------------------------------------------
// Problem constants
// ---------------------------------------------------------------------------
namespace {
constexpr int kB   = 8;
constexpr int kN   = 4096;
constexpr int kE   = 128;   // Din  (GEMM K)
constexpr int kF   = 256;   // Dout (GEMM M)
constexpr int kPTS = 32;    // points per block
constexpr int kM   = 3 * kPTS;  // 96 = GEMM N

// smem layout (bytes)
constexpr int AT_STRIDE = 272;              // a-tile row stride (136 bf16); 68 % 32 banks = 4
constexpr int OFF_AH    = 0;                // a hi [96][136] bf16 -> 26112 B
constexpr int OFF_AL    = 26112;            // a lo
constexpr int W_STRIDE  = 80;               // w chunk row stride (40 bf16); 20 % 32 banks
constexpr int OFF_WH    = 52224;            // W chunk hi [256][40] -> 20480 B
constexpr int OFF_WL    = OFF_WH + 20480;   // W chunk lo
// result regions (f32, row stride RES_S floats)
constexpr int RES_S     = 100;
constexpr int OFF_RD    = 0;                // d overlays dead a+w tiles (needs 102400)
constexpr int OFF_RX    = 102400;           // x region [256][100] f32 = 102400 B
constexpr int SMEM_BYTES = OFF_RX + kF * RES_S * 4;   // 204800 B
}

// ---------------------------------------------------------------------------
// Per-launch folded weights (device globals — no allocation allowed)
// ---------------------------------------------------------------------------
__device__ float g_Mc[kF * kE];   // Mc = A + B + C       [f][e]
__device__ float g_W2[kF * kE];   // W2 = W @ Mc          [f][e]
__device__ __align__(16) __nv_bfloat16 g_McHi[kF * kE];
__device__ __align__(16) __nv_bfloat16 g_McLo[kF * kE];
__device__ __align__(16) __nv_bfloat16 g_W2Hi[kF * kE];
__device__ __align__(16) __nv_bfloat16 g_W2Lo[kF * kE];

// ---------------------------------------------------------------------------
// Prep kernels
// ---------------------------------------------------------------------------
__global__ void prep_mc(const float* __restrict__ Am, const float* __restrict__ Bm,
                        const float* __restrict__ Cm) {
    const int i = blockIdx.x * 256 + threadIdx.x;
    g_Mc[i] = Am[i] + Bm[i] + Cm[i];
}

__global__ __launch_bounds__(128)
void prep_w2(const float* __restrict__ Wd) {
    __shared__ float wrow[kF];
    const int o = blockIdx.x;
    const int e = threadIdx.x;
    for (int c = threadIdx.x; c < kF; c += 128) wrow[c] = Wd[o * kF + c];
    __syncthreads();
    float acc = 0.0f;
    #pragma unroll 8
    for (int c = 0; c < kF; ++c)
        acc = fmaf(wrow[c], g_Mc[c * kE + e], acc);
    g_W2[o * kE + e] = acc;
}

__global__ void prep_split() {
    const int i = blockIdx.x * 256 + threadIdx.x;
    {
        const float v = g_Mc[i];
        const __nv_bfloat16 hi = __float2bfloat16(v);
        g_McHi[i] = hi;
        g_McLo[i] = __float2bfloat16(v - __bfloat162float(hi));
    }
    {
        const float v = g_W2[i];
        const __nv_bfloat16 hi = __float2bfloat16(v);
        g_W2Hi[i] = hi;
        g_W2Lo[i] = __float2bfloat16(v - __bfloat162float(hi));
    }
}

// ---------------------------------------------------------------------------
// PTX helpers (all sm_75/sm_80 baseline — compile under compute_103)
// ---------------------------------------------------------------------------
__device__ __forceinline__ uint32_t smem_u32(const void* p) {
    uint32_t a;
    asm("{ .reg .u64 t; cvta.to.shared.u64 t, %1; cvt.u32.u64 %0, t; }" : "=r"(a) : "l"(p));
    return a;
}

__device__ __forceinline__ void mma16816(float (&c)[4], const uint32_t (&a)[4],
                                         const uint32_t (&b)[2]) {
    asm volatile(
        "mma.sync.aligned.m16n8k16.row.col.f32.bf16.bf16.f32 "
        "{%0,%1,%2,%3}, {%4,%5,%6,%7}, {%8,%9}, {%0,%1,%2,%3};"
        : "+f"(c[0]), "+f"(c[1]), "+f"(c[2]), "+f"(c[3])
        : "r"(a[0]), "r"(a[1]), "r"(a[2]), "r"(a[3]), "r"(b[0]), "r"(b[1]));
}

__device__ __forceinline__ void ldsm4(uint32_t& r0, uint32_t& r1, uint32_t& r2,
                                      uint32_t& r3, uint32_t addr) {
    asm volatile("ldmatrix.sync.aligned.m8n8.x4.shared.b16 {%0,%1,%2,%3}, [%4];"
                 : "=r"(r0), "=r"(r1), "=r"(r2), "=r"(r3) : "r"(addr));
}

// ---------------------------------------------------------------------------
// Weight-chunk staging: 32-e chunks, register-prefetched
// ---------------------------------------------------------------------------
__device__ __forceinline__ void ldg_chunk(const __nv_bfloat16* __restrict__ gh,
                                          const __nv_bfloat16* __restrict__ gl,
                                          int ck, int t, uint4 (&pre)[8]) {
    #pragma unroll
    for (int it = 0; it < 4; ++it) {
        const int q = it * 256 + t;     // 0..1023
        const int f = q >> 2, j = q & 3;
        const size_t gi = (size_t)f * kE + ck * 32 + j * 8;
        pre[it]     = *reinterpret_cast<const uint4*>(gh + gi);
        pre[it + 4] = *reinterpret_cast<const uint4*>(gl + gi);
    }
}
__device__ __forceinline__ void sts_chunk(char* smem, int t, const uint4 (&pre)[8]) {
    #pragma unroll
    for (int it = 0; it < 4; ++it) {
        const int q = it * 256 + t;
        const int f = q >> 2, j = q & 3;
        *reinterpret_cast<uint4*>(smem + OFF_WH + f * W_STRIDE + j * 16) = pre[it];
        *reinterpret_cast<uint4*>(smem + OFF_WL + f * W_STRIDE + j * 16) = pre[it + 4];
    }
}

// ---------------------------------------------------------------------------
// One GEMM phase (K=128 in 4 chunks of 32): acc += W(hi/lo) x a(hi/lo), 3-pass
// pre[] holds the current phase's chunk 0 on entry; on exit holds (nh,nl) chunk 0.
// ---------------------------------------------------------------------------
__device__ __forceinline__ void gemm_phase(char* smem, uint32_t sb,
        const __nv_bfloat16* __restrict__ gh, const __nv_bfloat16* __restrict__ gl,
        const __nv_bfloat16* __restrict__ nh, const __nv_bfloat16* __restrict__ nl,
        uint4 (&pre)[8], float (&acc)[2][12][4], int t, int wid, int lane, bool first)
{
    const int f0w = wid * 32;
    // B ldmatrix base: lanes 0-7 tile2p.b0, 8-15 tile2p.b1, 16-23 tile2p+1.b0, 24-31 .b1
    const uint32_t bBaseH = sb + OFF_AH
        + (uint32_t)((((lane >> 4) << 3) + (lane & 7)) * AT_STRIDE)
        + (uint32_t)(((lane >> 3) & 1) << 4);
    const uint32_t bBaseL = bBaseH + (OFF_AL - OFF_AH);
    // A ldmatrix base: lanes 0-15 rows, lanes/16 = k-half
    const uint32_t aBaseH = sb + OFF_WH
        + (uint32_t)((f0w + (lane & 15)) * W_STRIDE) + (uint32_t)((lane >> 4) << 4);
    const uint32_t aBaseL = aBaseH + (OFF_WL - OFF_WH);

    #pragma unroll 1
    for (int ck = 0; ck < 4; ++ck) {
        if (!first || ck > 0) __syncthreads();   // prior chunk fully consumed
        sts_chunk(smem, t, pre);
        if (ck < 3)      ldg_chunk(gh, gl, ck + 1, t, pre);   // prefetch next chunk
        else if (nh)     ldg_chunk(nh, nl, 0, t, pre);        // prefetch next phase
        __syncthreads();

        #pragma unroll
        for (int kk = 0; kk < 2; ++kk) {
            const int keg = ck * 32 + kk * 16;

            uint32_t bh[12][2], bl[12][2];
            #pragma unroll
            for (int p = 0; p < 6; ++p) {
                const uint32_t bo = (uint32_t)(p * 16 * AT_STRIDE + keg * 2);
                ldsm4(bh[2*p][0], bh[2*p][1], bh[2*p+1][0], bh[2*p+1][1], bBaseH + bo);
                ldsm4(bl[2*p][0], bl[2*p][1], bl[2*p+1][0], bl[2*p+1][1], bBaseL + bo);
            }

            #pragma unroll
            for (int tf = 0; tf < 2; ++tf) {
                const uint32_t ao = (uint32_t)(tf * 16 * W_STRIDE + kk * 32);
                uint32_t ah[4], al[4];
                ldsm4(ah[0], ah[1], ah[2], ah[3], aBaseH + ao);
                ldsm4(al[0], al[1], al[2], al[3], aBaseL + ao);

                #pragma unroll
                for (int n = 0; n < 12; ++n) mma16816(acc[tf][n], ah, bh[n]);  // hi*hi
                #pragma unroll
                for (int n = 0; n < 12; ++n) mma16816(acc[tf][n], ah, bl[n]);  // hi*lo
                #pragma unroll
                for (int n = 0; n < 12; ++n) mma16816(acc[tf][n], al, bh[n]);  // lo*hi
            }
        }
    }
}

// scatter D-fragment accumulators into res[f][m] (stride RES_S floats)
__device__ __forceinline__ void scatter_acc(char* smem, int res_off,
                                            const float (&acc)[2][12][4],
                                            int wid, int lane) {
    const int f0w  = wid * 32;
    const int arow = lane >> 2;
    const int acol = (lane & 3) * 2;
    float* res = reinterpret_cast<float*>(smem + res_off);
    #pragma unroll
    for (int tf = 0; tf < 2; ++tf) {
        const int f = f0w + tf * 16 + arow;
        #pragma unroll
        for (int n = 0; n < 12; ++n) {
            const int m = n * 8 + acol;
            *reinterpret_cast<float2*>(res + f * RES_S + m) =
                make_float2(acc[tf][n][0], acc[tf][n][1]);
            *reinterpret_cast<float2*>(res + (f + 8) * RES_S + m) =
                make_float2(acc[tf][n][2], acc[tf][n][3]);
        }
    }
}

// ---------------------------------------------------------------------------
// Main fused kernel
// ---------------------------------------------------------------------------
__global__ __launch_bounds__(256, 1)
void affine_vn_mma(const float* __restrict__ X, const float* __restrict__ J,
                   float* __restrict__ out)
{
    extern __shared__ char smem[];
    const uint32_t sb = smem_u32(smem);
    const int t    = threadIdx.x;
    const int wid  = t >> 5;
    const int lane = t & 31;
    const int b    = blockIdx.y;
    const int n0   = blockIdx.x * kPTS;

    // prefetch Mc chunk 0 immediately — hides under phase 1
    uint4 pre[8];
    ldg_chunk(g_McHi, g_McLo, 0, t, pre);

    // ---- Phase 1: rotations + projections -> a-tile bf16 hi/lo [m][e] ----
    #pragma unroll 4
    for (int it = 0; it < 16; ++it) {
        const int q  = it * 256 + t;
        const int e  = q & (kE - 1);
        const int nl = q >> 7;
        const size_t base = (size_t)(b * kN + n0 + nl) * kE + e;
        const float* xp = X + base * 3;
        const float* jp = J + base * 6;
        const float x0 = xp[0], x1 = xp[1], x2 = xp[2];
        const float u0 = jp[0], u1 = jp[2], u2 = jp[4];
        const float v0 = jp[1], v1 = jp[3], v2 = jp[5];

        const float nn  = u0*u0 + u1*u1 + u2*u2;
        const float iv1 = rsqrtf(fmaxf(nn, 1e-24f));
        const float b10 = u0*iv1, b11 = u1*iv1, b12 = u2*iv1;
        const float dp  = b10*v0 + b11*v1 + b12*v2;
        const float w0 = v0 - dp*b10, w1 = v1 - dp*b11, w2 = v2 - dp*b12;
        const float wn  = w0*w0 + w1*w1 + w2*w2;
        const float iv2 = rsqrtf(fmaxf(wn, 1e-24f));
        const float b20 = w0*iv2, b21 = w1*iv2, b22 = w2*iv2;
        const float b30 = b11*b22 - b12*b21;
        const float b31 = b12*b20 - b10*b22;
        const float b32 = b10*b21 - b11*b20;

        float av[3];
        av[0] = x0*b10 + x1*b11 + x2*b12;
        av[1] = x0*b20 + x1*b21 + x2*b22;
        av[2] = x0*b30 + x1*b31 + x2*b32;

        #pragma unroll
        for (int i = 0; i < 3; ++i) {
            const int m = nl * 3 + i;
            const int off = m * AT_STRIDE + e * 2;
            const float v = av[i];
            const __nv_bfloat16 hi = __float2bfloat16(v);
            const __nv_bfloat16 lo = __float2bfloat16(v - __bfloat162float(hi));
            *reinterpret_cast<__nv_bfloat16*>(smem + OFF_AH + off) = hi;
            *reinterpret_cast<__nv_bfloat16*>(smem + OFF_AL + off) = lo;
        }
    }
    // no sync needed here: gemm_phase's first post-STS __syncthreads orders a-tile too

    // ---- Phase 2: x = Mc (x) a ----
    {
        float accx[2][12][4];
        #pragma unroll
        for (int i = 0; i < 2; ++i)
            #pragma unroll
            for (int j = 0; j < 12; ++j)
                #pragma unroll
                for (int k = 0; k < 4; ++k) accx[i][j][k] = 0.0f;
        gemm_phase(smem, sb, g_McHi, g_McLo, g_W2Hi, g_W2Lo, pre, accx,
                   t, wid, lane, /*first=*/true);
        scatter_acc(smem, OFF_RX, accx, wid, lane);   // x region dedicated: no race
    }

    // ---- Phase 3: d = W2 (x) a ----
    float accd[2][12][4];
    {
        #pragma unroll
        for (int i = 0; i < 2; ++i)
            #pragma unroll
            for (int j = 0; j < 12; ++j)
                #pragma unroll
                for (int k = 0; k < 4; ++k) accd[i][j][k] = 0.0f;
        gemm_phase(smem, sb, g_W2Hi, g_W2Lo, nullptr, nullptr, pre, accd,
                   t, wid, lane, /*first=*/false);
    }
    __syncthreads();                       // all warps done reading a/w tiles
    scatter_acc(smem, OFF_RD, accd, wid, lane);   // d overlays dead a+w region
    __syncthreads();

    // ---- Epilogue: VN-LeakyReLU on (x,d) triples + coalesced store [B,F,3,N] ----
    {
        const float* xs_base = reinterpret_cast<const float*>(smem + OFF_RX);
        const float* ds_base = reinterpret_cast<const float*>(smem + OFF_RD);
        #pragma unroll 4
        for (int r = 0; r < 32; ++r) {
            const int f = wid * 32 + r;
            const float* xs = xs_base + f * RES_S + 3 * lane;  // stride-3: conflict-free
            const float* ds = ds_base + f * RES_S + 3 * lane;
            const float X0 = xs[0], X1 = xs[1], X2 = xs[2];
            const float D0 = ds[0], D1 = ds[1], D2 = ds[2];
            const float dot = X0*D0 + X1*D1 + X2*D2;
            const float dsq = D0*D0 + D1*D1 + D2*D2;
            const float s = (dot >= 0.0f) ? 0.0f : 0.8f * dot * __fdividef(1.0f, dsq + 1e-6f);
            const size_t ob = ((size_t)(b * kF + f) * 3) * kN + n0 + lane;
            out[ob]                  = X0 - s * D0;
            out[ob + kN]             = X1 - s * D1;
            out[ob + 2 * (size_t)kN] = X2 - s * D2;
        }
    }
}

// ---------------------------------------------------------------------------
// Launcher
// ---------------------------------------------------------------------------
extern "C" void kernel_launch(void* const* d_in, const int* in_sizes, int n_in,
                              void* d_out, int out_size) {
    (void)in_sizes; (void)n_in; (void)out_size;
    const float* X  = (const float*)d_in[0];
    const float* J  = (const float*)d_in[1];
    const float* Am = (const float*)d_in[2];
    const float* Bm = (const float*)d_in[3];
    const float* Cm = (const float*)d_in[4];
    const float* Wd = (const float*)d_in[5];
    float* out = (float*)d_out;

    prep_mc<<<(kF * kE) / 256, 256>>>(Am, Bm, Cm);
    prep_w2<<<kF, 128>>>(Wd);
    prep_split<<<(kF * kE) / 256, 256>>>();

    cudaFuncSetAttribute(affine_vn_mma,
                         cudaFuncAttributeMaxDynamicSharedMemorySize, SMEM_BYTES);
    dim3 grid(kN / kPTS, kB);
    affine_vn_mma<<<grid, 256, SMEM_BYTES>>>(X, J, out);
}

// round 10
// speedup vs baseline: 1.5365x; 1.5365x over previous
#include <cuda_runtime.h>
#include <cuda_bf16.h>
#include <cstdint>

// ---------------------------------------------------------------------------
// Problem constants
// ---------------------------------------------------------------------------
namespace {
constexpr int kB   = 8;
constexpr int kN   = 4096;
constexpr int kE   = 128;   // Din  (GEMM K)
constexpr int kF   = 256;   // Dout (GEMM M)
constexpr int kPTS = 32;    // points per block
constexpr int kM   = 3 * kPTS;  // 96 = GEMM N

// smem layout (bytes)
constexpr int AT_STRIDE = 272;                  // a-tile row stride bytes (136 bf16), 272%128==16
constexpr int OFF_AH    = 0;                    // a hi [96][136] bf16  -> 26112 B
constexpr int OFF_AL    = 26112;                // a lo                 -> 26112 B
constexpr int W_STRIDE  = 144;                  // weight chunk row stride bytes (72 bf16)
constexpr int OFF_WH    = 52224;                // W chunk hi [256][72] -> 36864 B
constexpr int OFF_WL    = OFF_WH + 36864;       // W chunk lo           -> 36864 B
constexpr int RES_S     = 100;                  // result region row stride (floats)
constexpr int OFF_RX    = OFF_WL + 36864;       // x region [256][100] f32 = 102400 B
constexpr int OFF_RD    = 0;                    // d region overlays dead a/w tiles
constexpr int SMEM_BYTES = OFF_RX + kF * RES_S * 4;   // 228352 B
}

// ---------------------------------------------------------------------------
// Per-launch folded weights (device globals — no allocation allowed)
// ---------------------------------------------------------------------------
__device__ float g_Mc[kF * kE];   // Mc = A + B + C  [f][e]  (fp32, for W2 prep)
__device__ __align__(16) __nv_bfloat16 g_McHi[kF * kE];
__device__ __align__(16) __nv_bfloat16 g_McLo[kF * kE];
__device__ __align__(16) __nv_bfloat16 g_W2Hi[kF * kE];
__device__ __align__(16) __nv_bfloat16 g_W2Lo[kF * kE];

// ---------------------------------------------------------------------------
// Prep kernels (fused: fold + bf16 hi/lo split)
// ---------------------------------------------------------------------------
__global__ void prep_mc_split(const float* __restrict__ Am, const float* __restrict__ Bm,
                              const float* __restrict__ Cm) {
    const int i = blockIdx.x * 256 + threadIdx.x;
    const float v = Am[i] + Bm[i] + Cm[i];
    g_Mc[i] = v;
    const __nv_bfloat16 hi = __float2bfloat16(v);
    g_McHi[i] = hi;
    g_McLo[i] = __float2bfloat16(v - __bfloat162float(hi));
}

__global__ __launch_bounds__(128)
void prep_w2_split(const float* __restrict__ Wd) {
    __shared__ float wrow[kF];
    const int o = blockIdx.x;
    const int e = threadIdx.x;
    for (int c = threadIdx.x; c < kF; c += 128) wrow[c] = Wd[o * kF + c];
    __syncthreads();
    float acc = 0.0f;
    #pragma unroll 8
    for (int c = 0; c < kF; ++c)
        acc = fmaf(wrow[c], g_Mc[c * kE + e], acc);
    const int i = o * kE + e;
    const __nv_bfloat16 hi = __float2bfloat16(acc);
    g_W2Hi[i] = hi;
    g_W2Lo[i] = __float2bfloat16(acc - __bfloat162float(hi));
}

// ---------------------------------------------------------------------------
// mma.sync m16n8k16 bf16 (sm_80 baseline — compiles under compute_103)
// ---------------------------------------------------------------------------
__device__ __forceinline__ void mma16816(float (&c)[4], const uint32_t (&a)[4],
                                         const uint32_t (&b)[2]) {
    asm volatile(
        "mma.sync.aligned.m16n8k16.row.col.f32.bf16.bf16.f32 "
        "{%0,%1,%2,%3}, {%4,%5,%6,%7}, {%8,%9}, {%0,%1,%2,%3};"
        : "+f"(c[0]), "+f"(c[1]), "+f"(c[2]), "+f"(c[3])
        : "r"(a[0]), "r"(a[1]), "r"(a[2]), "r"(a[3]), "r"(b[0]), "r"(b[1]));
}

// ---------------------------------------------------------------------------
// One GEMM phase: warp tile = 64 f-rows x 6 n-tiles (48 m), 3-pass bf16 split
// acc[4 tf][6 n][4]
// ---------------------------------------------------------------------------
__device__ __forceinline__ void gemm_phase(char* smem,
                                           const __nv_bfloat16* __restrict__ ghi,
                                           const __nv_bfloat16* __restrict__ glo,
                                           float (&acc)[4][6][4],
                                           int t, int wid, int lane) {
    const int f0w  = (wid & 3) * 64;   // f-quarter
    const int mh   = (wid >> 2) * 48;  // m-half (rows of a-tile)
    const int arow = lane >> 2;        // 0..7
    const int acol = (lane & 3) * 2;   // 0,2,4,6

    #pragma unroll 1
    for (int ck = 0; ck < 2; ++ck) {
        // ---- stage weight chunk [256 f][64 e] hi+lo ----
        #pragma unroll 8
        for (int it = 0; it < 8; ++it) {
            const int q = it * 256 + t;          // 0..2047
            const int f = q >> 3, j = q & 7;
            const size_t gi = (size_t)f * kE + ck * 64 + j * 8;
            *reinterpret_cast<uint4*>(smem + OFF_WH + f * W_STRIDE + j * 16) =
                *reinterpret_cast<const uint4*>(ghi + gi);
            *reinterpret_cast<uint4*>(smem + OFF_WL + f * W_STRIDE + j * 16) =
                *reinterpret_cast<const uint4*>(glo + gi);
        }
        __syncthreads();

        #pragma unroll
        for (int kk = 0; kk < 4; ++kk) {
            const int keg = ck * 64 + kk * 16;   // global e base

            // ---- B fragments (a-tile hi/lo): 6 n-tiles ----
            uint32_t bh[6][2], bl[6][2];
            #pragma unroll
            for (int n = 0; n < 6; ++n) {
                const int ba = (mh + n * 8 + arow) * AT_STRIDE + (keg + acol) * 2;
                bh[n][0] = *reinterpret_cast<const uint32_t*>(smem + OFF_AH + ba);
                bh[n][1] = *reinterpret_cast<const uint32_t*>(smem + OFF_AH + ba + 16);
                bl[n][0] = *reinterpret_cast<const uint32_t*>(smem + OFF_AL + ba);
                bl[n][1] = *reinterpret_cast<const uint32_t*>(smem + OFF_AL + ba + 16);
            }

            #pragma unroll
            for (int tf = 0; tf < 4; ++tf) {
                const int wa = (f0w + tf * 16 + arow) * W_STRIDE + (kk * 16 + acol) * 2;
                uint32_t ah[4], al[4];
                ah[0] = *reinterpret_cast<const uint32_t*>(smem + OFF_WH + wa);
                ah[1] = *reinterpret_cast<const uint32_t*>(smem + OFF_WH + wa + 8 * W_STRIDE);
                ah[2] = *reinterpret_cast<const uint32_t*>(smem + OFF_WH + wa + 16);
                ah[3] = *reinterpret_cast<const uint32_t*>(smem + OFF_WH + wa + 8 * W_STRIDE + 16);
                al[0] = *reinterpret_cast<const uint32_t*>(smem + OFF_WL + wa);
                al[1] = *reinterpret_cast<const uint32_t*>(smem + OFF_WL + wa + 8 * W_STRIDE);
                al[2] = *reinterpret_cast<const uint32_t*>(smem + OFF_WL + wa + 16);
                al[3] = *reinterpret_cast<const uint32_t*>(smem + OFF_WL + wa + 8 * W_STRIDE + 16);

                #pragma unroll
                for (int n = 0; n < 6; ++n) mma16816(acc[tf][n], ah, bh[n]);  // hi*hi
                #pragma unroll
                for (int n = 0; n < 6; ++n) mma16816(acc[tf][n], ah, bl[n]);  // hi*lo
                #pragma unroll
                for (int n = 0; n < 6; ++n) mma16816(acc[tf][n], al, bh[n]);  // lo*hi
            }
        }
        __syncthreads();   // protect restage / region reuse
    }
}

// scatter D-fragment accumulators into res[f][m] (stride RES_S floats)
__device__ __forceinline__ void scatter_acc(char* smem, int res_off,
                                            const float (&acc)[4][6][4],
                                            int wid, int lane) {
    const int f0w  = (wid & 3) * 64;
    const int mh   = (wid >> 2) * 48;
    const int arow = lane >> 2;
    const int acol = (lane & 3) * 2;
    float* res = reinterpret_cast<float*>(smem + res_off);
    #pragma unroll
    for (int tf = 0; tf < 4; ++tf) {
        const int f = f0w + tf * 16 + arow;
        #pragma unroll
        for (int n = 0; n < 6; ++n) {
            const int m = mh + n * 8 + acol;
            *reinterpret_cast<float2*>(res + f * RES_S + m) =
                make_float2(acc[tf][n][0], acc[tf][n][1]);
            *reinterpret_cast<float2*>(res + (f + 8) * RES_S + m) =
                make_float2(acc[tf][n][2], acc[tf][n][3]);
        }
    }
}

// ---------------------------------------------------------------------------
// Main fused kernel
// ---------------------------------------------------------------------------
__global__ __launch_bounds__(256, 1)
void affine_vn_mma(const float* __restrict__ X, const float* __restrict__ J,
                   float* __restrict__ out)
{
    extern __shared__ char smem[];
    const int t    = threadIdx.x;
    const int wid  = t >> 5;
    const int lane = t & 31;
    const int b    = blockIdx.y;
    const int n0   = blockIdx.x * kPTS;

    // ---- Phase 1: rotations + projections -> a-tile bf16 hi/lo [m][e] ----
    #pragma unroll 4
    for (int it = 0; it < 16; ++it) {
        const int q  = it * 256 + t;
        const int e  = q & (kE - 1);
        const int nl = q >> 7;
        const size_t base = (size_t)(b * kN + n0 + nl) * kE + e;
        const float* xp = X + base * 3;
        const float* jp = J + base * 6;
        const float x0 = xp[0], x1 = xp[1], x2 = xp[2];
        const float u0 = jp[0], u1 = jp[2], u2 = jp[4];
        const float v0 = jp[1], v1 = jp[3], v2 = jp[5];

        const float nn  = u0*u0 + u1*u1 + u2*u2;
        const float iv1 = rsqrtf(fmaxf(nn, 1e-24f));
        const float b10 = u0*iv1, b11 = u1*iv1, b12 = u2*iv1;
        const float dp  = b10*v0 + b11*v1 + b12*v2;
        const float w0 = v0 - dp*b10, w1 = v1 - dp*b11, w2 = v2 - dp*b12;
        const float wn  = w0*w0 + w1*w1 + w2*w2;
        const float iv2 = rsqrtf(fmaxf(wn, 1e-24f));
        const float b20 = w0*iv2, b21 = w1*iv2, b22 = w2*iv2;
        const float b30 = b11*b22 - b12*b21;
        const float b31 = b12*b20 - b10*b22;
        const float b32 = b10*b21 - b11*b20;

        float av[3];
        av[0] = x0*b10 + x1*b11 + x2*b12;
        av[1] = x0*b20 + x1*b21 + x2*b22;
        av[2] = x0*b30 + x1*b31 + x2*b32;

        #pragma unroll
        for (int i = 0; i < 3; ++i) {
            const int m = nl * 3 + i;
            const int off = m * AT_STRIDE + e * 2;
            const float v = av[i];
            const __nv_bfloat16 hi = __float2bfloat16(v);
            const __nv_bfloat16 lo = __float2bfloat16(v - __bfloat162float(hi));
            *reinterpret_cast<__nv_bfloat16*>(smem + OFF_AH + off) = hi;
            *reinterpret_cast<__nv_bfloat16*>(smem + OFF_AL + off) = lo;
        }
    }
    __syncthreads();

    // ---- Phase 2: x = Mc (x) a ----
    {
        float accx[4][6][4];
        #pragma unroll
        for (int i = 0; i < 4; ++i)
            #pragma unroll
            for (int j = 0; j < 6; ++j)
                #pragma unroll
                for (int k = 0; k < 4; ++k) accx[i][j][k] = 0.0f;
        gemm_phase(smem, g_McHi, g_McLo, accx, t, wid, lane);
        scatter_acc(smem, OFF_RX, accx, wid, lane);   // x region dedicated: no race
    }

    // ---- Phase 3: d = W2 (x) a ----
    {
        float accd[4][6][4];
        #pragma unroll
        for (int i = 0; i < 4; ++i)
            #pragma unroll
            for (int j = 0; j < 6; ++j)
                #pragma unroll
                for (int k = 0; k < 4; ++k) accd[i][j][k] = 0.0f;
        gemm_phase(smem, g_W2Hi, g_W2Lo, accd, t, wid, lane);
        // a/w tiles dead now (gemm_phase ends with __syncthreads) -> overlay d at offset 0
        scatter_acc(smem, OFF_RD, accd, wid, lane);
    }
    __syncthreads();

    // ---- Epilogue: VN-LeakyReLU on (x,d) triples + coalesced store [B,F,3,N] ----
    {
        const float* xs_base = reinterpret_cast<const float*>(smem + OFF_RX);
        const float* ds_base = reinterpret_cast<const float*>(smem + OFF_RD);
        #pragma unroll 4
        for (int r = 0; r < 32; ++r) {
            const int f = wid * 32 + r;
            const float* xs = xs_base + f * RES_S + 3 * lane;  // stride-3: conflict-free
            const float* ds = ds_base + f * RES_S + 3 * lane;
            const float X0 = xs[0], X1 = xs[1], X2 = xs[2];
            const float D0 = ds[0], D1 = ds[1], D2 = ds[2];
            const float dot = X0*D0 + X1*D1 + X2*D2;
            const float dsq = D0*D0 + D1*D1 + D2*D2;
            const float s = (dot >= 0.0f) ? 0.0f : 0.8f * dot * __fdividef(1.0f, dsq + 1e-6f);
            const size_t ob = ((size_t)(b * kF + f) * 3) * kN + n0 + lane;
            out[ob]                  = X0 - s * D0;
            out[ob + kN]             = X1 - s * D1;
            out[ob + 2 * (size_t)kN] = X2 - s * D2;
        }
    }
}

// ---------------------------------------------------------------------------
// Launcher
// ---------------------------------------------------------------------------
extern "C" void kernel_launch(void* const* d_in, const int* in_sizes, int n_in,
                              void* d_out, int out_size) {
    (void)in_sizes; (void)n_in; (void)out_size;
    const float* X  = (const float*)d_in[0];
    const float* J  = (const float*)d_in[1];
    const float* Am = (const float*)d_in[2];
    const float* Bm = (const float*)d_in[3];
    const float* Cm = (const float*)d_in[4];
    const float* Wd = (const float*)d_in[5];
    float* out = (float*)d_out;

    prep_mc_split<<<(kF * kE) / 256, 256>>>(Am, Bm, Cm);
    prep_w2_split<<<kF, 128>>>(Wd);

    cudaFuncSetAttribute(affine_vn_mma,
                         cudaFuncAttributeMaxDynamicSharedMemorySize, SMEM_BYTES);
    dim3 grid(kN / kPTS, kB);
    affine_vn_mma<<<grid, 256, SMEM_BYTES>>>(X, J, out);
}

// round 11
// speedup vs baseline: 1.8874x; 1.2284x over previous
#include <cuda_runtime.h>
#include <cstdint>

// ---------------------------------------------------------------------------
// Problem constants
// ---------------------------------------------------------------------------
namespace {
constexpr int kB   = 8;
constexpr int kN   = 4096;
constexpr int kE   = 128;   // Din  (GEMM K)
constexpr int kF   = 256;   // Dout (GEMM M)
constexpr int kPTS = 32;    // points per block
constexpr int kM   = 3 * kPTS;  // 96 = GEMM N

// smem layout
constexpr int AT_S    = 132;                 // a-tile row stride (f32 words); 132%32=4 -> conflict-free frags
constexpr int OFF_A   = 0;
constexpr int A_BYTES = kM * AT_S * 4;       // 96*528 = 50688
constexpr int W_S     = 36;                  // weight chunk row stride (words): 32 data + 4 pad
constexpr int W_BYTES = kF * W_S * 4;        // 36864
constexpr int OFF_W0  = A_BYTES;             // 50688
constexpr int OFF_W1  = OFF_W0 + W_BYTES;    // 87552
constexpr int RES_S   = 100;                 // result row stride (f32 words)
constexpr int OFF_RX  = OFF_W1 + W_BYTES;    // 124416 (x region, dedicated)
constexpr int OFF_RD  = 0;                   // d region overlays dead a-tile + w-bufs (needs 102400 <= 124416)
constexpr int SMEM_BYTES = OFF_RX + kF * RES_S * 4;   // 226816 B
}

// ---------------------------------------------------------------------------
// Per-launch folded weights (device globals — no allocation allowed)
// ---------------------------------------------------------------------------
__device__ float g_Mc [kF * kE];   // full f32 Mc = A+B+C (for accurate W2 fold)
__device__ float g_McT[kF * kE];   // tf32-rounded Mc
__device__ float g_W2T[kF * kE];   // tf32-rounded W2 = W @ Mc

// ---------------------------------------------------------------------------
// Small helpers
// ---------------------------------------------------------------------------
__device__ __forceinline__ float to_tf32(float v) {
    uint32_t r;
    asm("cvt.rna.tf32.f32 %0, %1;" : "=r"(r) : "f"(v));
    return __uint_as_float(r);
}
__device__ __forceinline__ uint32_t smem_u32(const void* p) {
    uint32_t a;
    asm("{ .reg .u64 t; cvta.to.shared.u64 t, %1; cvt.u32.u64 %0, t; }" : "=r"(a) : "l"(p));
    return a;
}
__device__ __forceinline__ void cp16(uint32_t dst, const float* src) {
    asm volatile("cp.async.cg.shared.global [%0], [%1], 16;"
                 :: "r"(dst), "l"(__cvta_generic_to_global(src)) : "memory");
}
__device__ __forceinline__ void cp_commit() {
    asm volatile("cp.async.commit_group;" ::: "memory");
}
template <int N>
__device__ __forceinline__ void cp_wait() {
    asm volatile("cp.async.wait_group %0;" :: "n"(N) : "memory");
}

// mma.sync m16n8k8 tf32 (sm_80 baseline — compiles under compute_103)
__device__ __forceinline__ void mma_tf32(float (&c)[4], const uint32_t (&a)[4],
                                         const uint32_t (&b)[2]) {
    asm volatile(
        "mma.sync.aligned.m16n8k8.row.col.f32.tf32.tf32.f32 "
        "{%0,%1,%2,%3}, {%4,%5,%6,%7}, {%8,%9}, {%0,%1,%2,%3};"
        : "+f"(c[0]), "+f"(c[1]), "+f"(c[2]), "+f"(c[3])
        : "r"(a[0]), "r"(a[1]), "r"(a[2]), "r"(a[3]), "r"(b[0]), "r"(b[1]));
}

// ---------------------------------------------------------------------------
// Prep kernels
// ---------------------------------------------------------------------------
__global__ void prep_mc(const float* __restrict__ Am, const float* __restrict__ Bm,
                        const float* __restrict__ Cm) {
    const int i = blockIdx.x * 256 + threadIdx.x;
    const float v = Am[i] + Bm[i] + Cm[i];
    g_Mc[i]  = v;
    g_McT[i] = to_tf32(v);
}

__global__ __launch_bounds__(128)
void prep_w2(const float* __restrict__ Wd) {
    __shared__ float wrow[kF];
    const int o = blockIdx.x;
    const int e = threadIdx.x;
    for (int c = threadIdx.x; c < kF; c += 128) wrow[c] = Wd[o * kF + c];
    __syncthreads();
    float acc = 0.0f;
    #pragma unroll 8
    for (int c = 0; c < kF; ++c)
        acc = fmaf(wrow[c], g_Mc[c * kE + e], acc);
    g_W2T[o * kE + e] = to_tf32(acc);
}

// ---------------------------------------------------------------------------
// Pipeline pieces
// ---------------------------------------------------------------------------
// stage one 32-e weight chunk [256 f][32 e] f32 into w buffer (async)
__device__ __forceinline__ void issue_chunk(uint32_t sb, int woff,
                                            const float* __restrict__ gsrc,
                                            int eoff, int t) {
    #pragma unroll
    for (int it = 0; it < 8; ++it) {
        const int q = it * 256 + t;     // 0..2047
        const int f = q >> 3, j = q & 7;
        cp16(sb + woff + f * (W_S * 4) + j * 16,
             gsrc + (size_t)f * kE + eoff + j * 4);
    }
}

// compute one 32-e chunk: acc[4 tf][6 n][4] += W_chunk x a-tile (tf32 single pass)
__device__ __forceinline__ void compute_chunk(const char* smem, int woff, int eck,
                                              float (&acc)[4][6][4],
                                              int wid, int lane) {
    const int f0w = (wid & 3) * 64;     // f-quarter
    const int mh  = (wid >> 2) * 48;    // m-half
    const int g   = lane >> 2;          // 0..7
    const int k   = lane & 3;           // 0..3
    const uint32_t* as = reinterpret_cast<const uint32_t*>(smem + OFF_A);
    const uint32_t* ws = reinterpret_cast<const uint32_t*>(smem + woff);

    #pragma unroll
    for (int k8 = 0; k8 < 4; ++k8) {
        const int colA = eck * 32 + k8 * 8 + k;   // a-tile global e column

        uint32_t b[6][2];
        #pragma unroll
        for (int n = 0; n < 6; ++n) {
            const int row = (mh + n * 8 + g) * AT_S;
            b[n][0] = as[row + colA];
            b[n][1] = as[row + colA + 4];
        }

        #pragma unroll
        for (int tf = 0; tf < 4; ++tf) {
            const int r0 = (f0w + tf * 16 + g) * W_S;
            const int c0 = k8 * 8 + k;
            uint32_t a[4];
            a[0] = ws[r0 + c0];
            a[1] = ws[r0 + 8 * W_S + c0];
            a[2] = ws[r0 + c0 + 4];
            a[3] = ws[r0 + 8 * W_S + c0 + 4];
            #pragma unroll
            for (int n = 0; n < 6; ++n) mma_tf32(acc[tf][n], a, b[n]);
        }
    }
}

// scatter D-fragment accumulators into res[f][m] (stride RES_S floats)
__device__ __forceinline__ void scatter_acc(char* smem, int res_off,
                                            const float (&acc)[4][6][4],
                                            int wid, int lane) {
    const int f0w  = (wid & 3) * 64;
    const int mh   = (wid >> 2) * 48;
    const int arow = lane >> 2;
    const int acol = (lane & 3) * 2;
    float* res = reinterpret_cast<float*>(smem + res_off);
    #pragma unroll
    for (int tf = 0; tf < 4; ++tf) {
        const int f = f0w + tf * 16 + arow;
        #pragma unroll
        for (int n = 0; n < 6; ++n) {
            const int m = mh + n * 8 + acol;
            *reinterpret_cast<float2*>(res + f * RES_S + m) =
                make_float2(acc[tf][n][0], acc[tf][n][1]);
            *reinterpret_cast<float2*>(res + (f + 8) * RES_S + m) =
                make_float2(acc[tf][n][2], acc[tf][n][3]);
        }
    }
}

// ---------------------------------------------------------------------------
// Main fused kernel
// ---------------------------------------------------------------------------
__global__ __launch_bounds__(256, 1)
void affine_vn_tf32(const float* __restrict__ X, const float* __restrict__ J,
                    float* __restrict__ out)
{
    extern __shared__ char smem[];
    const uint32_t sb = smem_u32(smem);
    const int t    = threadIdx.x;
    const int wid  = t >> 5;
    const int lane = t & 31;
    const int b    = blockIdx.y;
    const int n0   = blockIdx.x * kPTS;

    // kick off weight chunk 0 (Mc e[0:32)) — streams to smem during phase 1
    issue_chunk(sb, OFF_W0, g_McT, 0, t);
    cp_commit();

    // ---- Phase 1: rotations + projections -> a-tile tf32 [m][e] ----
    float* a_s = reinterpret_cast<float*>(smem + OFF_A);
    #pragma unroll 4
    for (int it = 0; it < 16; ++it) {
        const int q  = it * 256 + t;
        const int e  = q & (kE - 1);
        const int nl = q >> 7;
        const size_t base = (size_t)(b * kN + n0 + nl) * kE + e;
        const float* xp = X + base * 3;
        const float* jp = J + base * 6;
        const float x0 = xp[0], x1 = xp[1], x2 = xp[2];
        const float u0 = jp[0], u1 = jp[2], u2 = jp[4];
        const float v0 = jp[1], v1 = jp[3], v2 = jp[5];

        const float nn  = u0*u0 + u1*u1 + u2*u2;
        const float iv1 = rsqrtf(fmaxf(nn, 1e-24f));
        const float b10 = u0*iv1, b11 = u1*iv1, b12 = u2*iv1;
        const float dp  = b10*v0 + b11*v1 + b12*v2;
        const float w0 = v0 - dp*b10, w1 = v1 - dp*b11, w2 = v2 - dp*b12;
        const float wn  = w0*w0 + w1*w1 + w2*w2;
        const float iv2 = rsqrtf(fmaxf(wn, 1e-24f));
        const float b20 = w0*iv2, b21 = w1*iv2, b22 = w2*iv2;
        const float b30 = b11*b22 - b12*b21;
        const float b31 = b12*b20 - b10*b22;
        const float b32 = b10*b21 - b11*b20;

        const int m0 = nl * 3;
        a_s[(m0 + 0) * AT_S + e] = to_tf32(x0*b10 + x1*b11 + x2*b12);
        a_s[(m0 + 1) * AT_S + e] = to_tf32(x0*b20 + x1*b21 + x2*b22);
        a_s[(m0 + 2) * AT_S + e] = to_tf32(x0*b30 + x1*b31 + x2*b32);
    }

    // ---- Phase 2: x = Mc (x) a   (chunks 0..3, double-buffered) ----
    float accx[4][6][4];
    #pragma unroll
    for (int i = 0; i < 4; ++i)
        #pragma unroll
        for (int j = 0; j < 6; ++j)
            #pragma unroll
            for (int q = 0; q < 4; ++q) accx[i][j][q] = 0.0f;

    #pragma unroll
    for (int ck = 0; ck < 4; ++ck) {
        __syncthreads();   // (ck==0: publishes a-tile) buffer (ck+1)&1 free
        if (ck < 3) issue_chunk(sb, ((ck + 1) & 1) ? OFF_W1 : OFF_W0, g_McT, (ck + 1) * 32, t);
        else        issue_chunk(sb, OFF_W0, g_W2T, 0, t);   // prefetch W2 chunk 0
        cp_commit();
        cp_wait<1>();      // chunk ck has landed
        __syncthreads();
        compute_chunk(smem, (ck & 1) ? OFF_W1 : OFF_W0, ck, accx, wid, lane);
    }
    scatter_acc(smem, OFF_RX, accx, wid, lane);   // dedicated region, thread-private: no sync

    // ---- Phase 3: d = W2 (x) a   (chunks 4..7) ----
    float accd[4][6][4];
    #pragma unroll
    for (int i = 0; i < 4; ++i)
        #pragma unroll
        for (int j = 0; j < 6; ++j)
            #pragma unroll
            for (int q = 0; q < 4; ++q) accd[i][j][q] = 0.0f;

    #pragma unroll
    for (int ck = 4; ck < 8; ++ck) {
        __syncthreads();
        if (ck < 7) {
            issue_chunk(sb, ((ck + 1) & 1) ? OFF_W1 : OFF_W0, g_W2T, (ck - 3) * 32, t);
            cp_commit();
            cp_wait<1>();
        } else {
            cp_wait<0>();
        }
        __syncthreads();
        compute_chunk(smem, (ck & 1) ? OFF_W1 : OFF_W0, ck - 4, accd, wid, lane);
    }

    __syncthreads();                        // all warps done with a-tile + w-bufs
    scatter_acc(smem, OFF_RD, accd, wid, lane);   // d overlays dead region
    __syncthreads();

    // ---- Epilogue: VN-LeakyReLU on (x,d) triples + coalesced store [B,F,3,N] ----
    {
        const float* xs_base = reinterpret_cast<const float*>(smem + OFF_RX);
        const float* ds_base = reinterpret_cast<const float*>(smem + OFF_RD);
        #pragma unroll 4
        for (int r = 0; r < 32; ++r) {
            const int f = wid * 32 + r;
            const float* xs = xs_base + f * RES_S + 3 * lane;  // stride-3: conflict-free
            const float* ds = ds_base + f * RES_S + 3 * lane;
            const float X0 = xs[0], X1 = xs[1], X2 = xs[2];
            const float D0 = ds[0], D1 = ds[1], D2 = ds[2];
            const float dot = X0*D0 + X1*D1 + X2*D2;
            const float dsq = D0*D0 + D1*D1 + D2*D2;
            const float s = (dot >= 0.0f) ? 0.0f : 0.8f * dot * __fdividef(1.0f, dsq + 1e-6f);
            const size_t ob = ((size_t)(b * kF + f) * 3) * kN + n0 + lane;
            out[ob]                  = X0 - s * D0;
            out[ob + kN]             = X1 - s * D1;
            out[ob + 2 * (size_t)kN] = X2 - s * D2;
        }
    }
}

// ---------------------------------------------------------------------------
// Launcher
// ---------------------------------------------------------------------------
extern "C" void kernel_launch(void* const* d_in, const int* in_sizes, int n_in,
                              void* d_out, int out_size) {
    (void)in_sizes; (void)n_in; (void)out_size;
    const float* X  = (const float*)d_in[0];
    const float* J  = (const float*)d_in[1];
    const float* Am = (const float*)d_in[2];
    const float* Bm = (const float*)d_in[3];
    const float* Cm = (const float*)d_in[4];
    const float* Wd = (const float*)d_in[5];
    float* out = (float*)d_out;

    prep_mc<<<(kF * kE) / 256, 256>>>(Am, Bm, Cm);
    prep_w2<<<kF, 128>>>(Wd);

    cudaFuncSetAttribute(affine_vn_tf32,
                         cudaFuncAttributeMaxDynamicSharedMemorySize, SMEM_BYTES);
    dim3 grid(kN / kPTS, kB);
    affine_vn_tf32<<<grid, 256, SMEM_BYTES>>>(X, J, out);
}